// round 13
// baseline (speedup 1.0000x reference)
#include <cuda_runtime.h>
#include <cstdint>

#define N_INST 64
#define HW 64000   // 200*320
#define MASK_ELEMS (N_INST * HW)

#define TILE_P 256          // pixels per CTA tile
#define NTILES 250          // 64000 / 256
#define KC 16               // k-chunk (j rows) per stage

// Scratch (no cudaMalloc):
__device__ unsigned long long g_Odup[N_INST * N_INST];  // (O,O) pairs, [j][i]
__device__ unsigned long long g_tick;                   // monotone ticket (zero-init)

__device__ __forceinline__ float sigmoidf_(float x) {
    return __fdividef(1.0f, 1.0f + __expf(-x));
}

__device__ __forceinline__ unsigned long long pack2_(float lo, float hi) {
    unsigned long long d;
    asm("mov.b64 %0, {%1, %2};" : "=l"(d) : "f"(lo), "f"(hi));
    return d;
}

__device__ __forceinline__ void unpack2_(unsigned long long v, float& lo, float& hi) {
    asm("mov.b64 {%0, %1}, %2;" : "=f"(lo), "=f"(hi) : "l"(v));
}

__device__ __forceinline__ unsigned long long fma2_(unsigned long long a,
                                                    unsigned long long b,
                                                    unsigned long long c) {
    unsigned long long d;
    asm("fma.rn.f32x2 %0, %1, %2, %3;" : "=l"(d) : "l"(a), "l"(b), "l"(c));
    return d;
}

// ---------------------------------------------------------------------------
// One relation task per warp: task < 2016 -> unordered pair (i<j), both
// orientations; 2016..2079 -> diagonal zero. No returns (barrier safety).
// ---------------------------------------------------------------------------
__device__ void relation_task(int task, int lane,
                              const float* __restrict__ bbox,
                              const int*   __restrict__ cls_idx,
                              const float* __restrict__ U_w,
                              const float* __restrict__ V_w,
                              const float* __restrict__ Wc_w,
                              const float* __restrict__ P_w,
                              float* __restrict__ out_O)
{
    const int NPAIR = (N_INST * (N_INST - 1)) / 2;   // 2016

    if (task >= NPAIR) {                              // diagonal zeros
        if (lane == 0) {
            int i = task - NPAIR;
            out_O[i * 64 + i]  = 0.f;
            g_Odup[i * 64 + i] = 0ull;
        }
        return;   // returns from helper only; caller still reaches barrier
    }

    // decode i < j from triangular index: task = j*(j-1)/2 + i
    int j = (int)((1.0f + sqrtf(8.0f * (float)task + 1.0f)) * 0.5f);
    while (j * (j - 1) / 2 > task) j--;
    while ((j + 1) * j / 2 <= task) j++;
    int i = task - j * (j - 1) / 2;

    int ki = cls_idx[i] - 1;
    int kj = cls_idx[j] - 1;

    float s_ij = 0.f, s_ji = 0.f;

    #pragma unroll
    for (int c = lane; c < 256; c += 32) {
        float ui = fmaxf(U_w[c * 80 + ki], 0.f);
        float uj = fmaxf(U_w[c * 80 + kj], 0.f);
        float vi = fmaxf(V_w[c * 80 + ki], 0.f);
        float vj = fmaxf(V_w[c * 80 + kj], 0.f);
        float p  = P_w[c];
        s_ij += ui * vj * p;
        s_ji += uj * vi * p;
    }

    float x0i = bbox[i * 5 + 1], y0i = bbox[i * 5 + 2];
    float x1i = bbox[i * 5 + 3], y1i = bbox[i * 5 + 4];
    float x0j = bbox[j * 5 + 1], y0j = bbox[j * 5 + 2];
    float x1j = bbox[j * 5 + 3], y1j = bbox[j * 5 + 4];
    float wi = x1i - x0i + 1.f, hi = y1i - y0i + 1.f;
    float wj = x1j - x0j + 1.f, hj = y1j - y0j + 1.f;
    float xci = x0i + 0.5f * wi, yci = y0i + 0.5f * hi;
    float xcj = x0j + 0.5f * wj, ycj = y0j + 0.5f * hj;

    float dx_ij = -(xci - xcj) / wi, dy_ij = -(yci - ycj) / hi;
    float dw_ij = __logf(wj / wi),   dh_ij = __logf(hj / hi);
    float dx_ji = -(xcj - xci) / wj, dy_ji = -(ycj - yci) / hj;
    float dw_ji = __logf(wi / wj),   dh_ji = __logf(hi / hj);

    #pragma unroll
    for (int o = lane; o < 128; o += 32) {
        float4 w4 = *reinterpret_cast<const float4*>(&Wc_w[o * 4]);
        float p = P_w[256 + o];
        float a = dx_ij * w4.x + dy_ij * w4.y + dw_ij * w4.z + dh_ij * w4.w;
        float b = dx_ji * w4.x + dy_ji * w4.y + dw_ji * w4.z + dh_ji * w4.w;
        s_ij += fmaxf(a, 0.f) * p;
        s_ji += fmaxf(b, 0.f) * p;
    }

    #pragma unroll
    for (int off = 16; off; off >>= 1) {
        s_ij += __shfl_xor_sync(0xffffffffu, s_ij, off);
        s_ji += __shfl_xor_sync(0xffffffffu, s_ji, off);
    }

    if (lane == 0) {
        float r_ij = sigmoidf_(s_ij);
        float r_ji = sigmoidf_(s_ji);
        float o_ij = fmaxf(r_ij - r_ji, 0.f);
        float o_ji = fmaxf(r_ji - r_ij, 0.f);
        out_O[i * 64 + j]  = o_ij;
        out_O[j * 64 + i]  = o_ji;
        g_Odup[j * 64 + i] = pack2_(o_ij, o_ij);
        g_Odup[i * 64 + j] = pack2_(o_ji, o_ji);
    }
}

// ---------------------------------------------------------------------------
// Fused kernel: stage t chunk 0 -> relation tasks -> device-wide ticket
// barrier -> Od copy -> tiled GEMM (R9 config: 8 warps, thread tile 8i x 8p,
// 32 FFMA2 per k) -> epilogue. All 250 CTAs co-resident (regs<=128 via
// launch_bounds, smem 48KB), so the spin cannot deadlock. Ticket is
// monotone: target = (old/250+1)*250, valid across graph replays, no reset.
// ---------------------------------------------------------------------------
__global__ void __launch_bounds__(256, 2)
fused_kernel(const float* __restrict__ mask,
             const float* __restrict__ bbox,
             const int*   __restrict__ cls_idx,
             const float* __restrict__ U_w,
             const float* __restrict__ V_w,
             const float* __restrict__ Wc_w,
             const float* __restrict__ P_w,
             float* __restrict__ out,
             float* __restrict__ out_O)
{
    __shared__ __align__(16) unsigned long long Od[64 * 64];  // 32KB
    __shared__ __align__(16) float tS[KC * TILE_P];           // 16KB

    int tid  = threadIdx.x;
    int w    = tid >> 5;        // warp 0..7 -> i rows [w*8, w*8+8)
    int lane = tid & 31;
    int pbase = blockIdx.x * TILE_P;

    // A) stage chunk 0 of t = sigmoid(mask) (before the barrier; overlaps B)
    #pragma unroll
    for (int s = tid; s < (KC * TILE_P) / 4; s += 256) {
        int row = s >> 6, q = s & 63;
        float4 m = *reinterpret_cast<const float4*>(
            mask + (size_t)row * HW + pbase + q * 4);
        float4 t;
        t.x = sigmoidf_(m.x);
        t.y = sigmoidf_(m.y);
        t.z = sigmoidf_(m.z);
        t.w = sigmoidf_(m.w);
        *reinterpret_cast<float4*>(&tS[row * TILE_P + q * 4]) = t;
    }

    // B) relation tasks: 2080 warp-tasks over 250 blocks x 8 warps
    for (int task = blockIdx.x * 8 + w; task < 2080; task += 2000)
        relation_task(task, lane, bbox, cls_idx, U_w, V_w, Wc_w, P_w, out_O);

    // C) device-wide ticket barrier (all CTAs resident -> no deadlock)
    if (tid == 0) {
        __threadfence();
        unsigned long long old = atomicAdd(&g_tick, 1ull);
        unsigned long long target = (old / NTILES + 1ull) * NTILES;
        while (*((volatile unsigned long long*)&g_tick) < target) { }
    }
    __syncthreads();

    // D) Od copy (L2 loads; g_Odup now complete)
    #pragma unroll
    for (int k = tid; k < 4096; k += 256) Od[k] = __ldcg(&g_Odup[k]);
    __syncthreads();

    // E) GEMM mainloop
    unsigned long long acc[32];
    #pragma unroll
    for (int k = 0; k < 32; k++) acc[k] = 0ull;

    #pragma unroll 1
    for (int kc = 0; kc < 4; kc++) {
        if (kc > 0) {
            __syncthreads();   // all warps done with previous chunk
            #pragma unroll
            for (int s = tid; s < (KC * TILE_P) / 4; s += 256) {
                int row = s >> 6, q = s & 63;
                float4 m = *reinterpret_cast<const float4*>(
                    mask + (size_t)(kc * KC + row) * HW + pbase + q * 4);
                float4 t;
                t.x = sigmoidf_(m.x);
                t.y = sigmoidf_(m.y);
                t.z = sigmoidf_(m.z);
                t.w = sigmoidf_(m.w);
                *reinterpret_cast<float4*>(&tS[row * TILE_P + q * 4]) = t;
            }
            __syncthreads();
        }

        #pragma unroll
        for (int k = 0; k < KC; k++) {
            const ulonglong2* trow =
                reinterpret_cast<const ulonglong2*>(&tS[k * TILE_P]);
            ulonglong2 tA = trow[lane];
            ulonglong2 tB = trow[32 + lane];
            const ulonglong2* orow = reinterpret_cast<const ulonglong2*>(
                &Od[(kc * KC + k) * 64 + w * 8]);
            ulonglong2 o01 = orow[0];
            ulonglong2 o23 = orow[1];
            ulonglong2 o45 = orow[2];
            ulonglong2 o67 = orow[3];

            acc[ 0] = fma2_(o01.x, tA.x, acc[ 0]);
            acc[ 1] = fma2_(o01.x, tA.y, acc[ 1]);
            acc[ 2] = fma2_(o01.x, tB.x, acc[ 2]);
            acc[ 3] = fma2_(o01.x, tB.y, acc[ 3]);
            acc[ 4] = fma2_(o01.y, tA.x, acc[ 4]);
            acc[ 5] = fma2_(o01.y, tA.y, acc[ 5]);
            acc[ 6] = fma2_(o01.y, tB.x, acc[ 6]);
            acc[ 7] = fma2_(o01.y, tB.y, acc[ 7]);
            acc[ 8] = fma2_(o23.x, tA.x, acc[ 8]);
            acc[ 9] = fma2_(o23.x, tA.y, acc[ 9]);
            acc[10] = fma2_(o23.x, tB.x, acc[10]);
            acc[11] = fma2_(o23.x, tB.y, acc[11]);
            acc[12] = fma2_(o23.y, tA.x, acc[12]);
            acc[13] = fma2_(o23.y, tA.y, acc[13]);
            acc[14] = fma2_(o23.y, tB.x, acc[14]);
            acc[15] = fma2_(o23.y, tB.y, acc[15]);
            acc[16] = fma2_(o45.x, tA.x, acc[16]);
            acc[17] = fma2_(o45.x, tA.y, acc[17]);
            acc[18] = fma2_(o45.x, tB.x, acc[18]);
            acc[19] = fma2_(o45.x, tB.y, acc[19]);
            acc[20] = fma2_(o45.y, tA.x, acc[20]);
            acc[21] = fma2_(o45.y, tA.y, acc[21]);
            acc[22] = fma2_(o45.y, tB.x, acc[22]);
            acc[23] = fma2_(o45.y, tB.y, acc[23]);
            acc[24] = fma2_(o67.x, tA.x, acc[24]);
            acc[25] = fma2_(o67.x, tA.y, acc[25]);
            acc[26] = fma2_(o67.x, tB.x, acc[26]);
            acc[27] = fma2_(o67.x, tB.y, acc[27]);
            acc[28] = fma2_(o67.y, tA.x, acc[28]);
            acc[29] = fma2_(o67.y, tA.y, acc[29]);
            acc[30] = fma2_(o67.y, tB.x, acc[30]);
            acc[31] = fma2_(o67.y, tB.y, acc[31]);
        }
    }

    // F) epilogue: new = m - m * sigma(m) * w  (sigma recomputed)
    #pragma unroll
    for (int r = 0; r < 8; r++) {
        int i = w * 8 + r;
        size_t base = (size_t)i * HW + pbase;

        float4 mA = *reinterpret_cast<const float4*>(mask + base + lane * 4);
        float4 mB = *reinterpret_cast<const float4*>(mask + base + (32 + lane) * 4);

        float a0, a1, a2, a3, b0, b1, b2, b3;
        unpack2_(acc[r * 4 + 0], a0, a1);
        unpack2_(acc[r * 4 + 1], a2, a3);
        unpack2_(acc[r * 4 + 2], b0, b1);
        unpack2_(acc[r * 4 + 3], b2, b3);

        float4 rA, rB;
        rA.x = mA.x - mA.x * sigmoidf_(mA.x) * a0;
        rA.y = mA.y - mA.y * sigmoidf_(mA.y) * a1;
        rA.z = mA.z - mA.z * sigmoidf_(mA.z) * a2;
        rA.w = mA.w - mA.w * sigmoidf_(mA.w) * a3;
        rB.x = mB.x - mB.x * sigmoidf_(mB.x) * b0;
        rB.y = mB.y - mB.y * sigmoidf_(mB.y) * b1;
        rB.z = mB.z - mB.z * sigmoidf_(mB.z) * b2;
        rB.w = mB.w - mB.w * sigmoidf_(mB.w) * b3;

        *reinterpret_cast<float4*>(out + base + lane * 4)        = rA;
        *reinterpret_cast<float4*>(out + base + (32 + lane) * 4) = rB;
    }
}

extern "C" void kernel_launch(void* const* d_in, const int* in_sizes, int n_in,
                              void* d_out, int out_size)
{
    const float* mask    = (const float*)d_in[0];
    const float* bbox    = (const float*)d_in[1];
    const int*   cls_idx = (const int*)  d_in[2];
    const float* U_w     = (const float*)d_in[3];
    const float* V_w     = (const float*)d_in[4];
    const float* Wc_w    = (const float*)d_in[5];
    const float* P_w     = (const float*)d_in[6];

    float* out_mask = (float*)d_out;                 // 4,096,000 elems
    float* out_O    = (float*)d_out + MASK_ELEMS;    // 4,096 elems

    fused_kernel<<<NTILES, 256>>>(mask, bbox, cls_idx, U_w, V_w, Wc_w, P_w,
                                  out_mask, out_O);
}

// round 14
// speedup vs baseline: 1.1480x; 1.1480x over previous
#include <cuda_runtime.h>
#include <cstdint>

#define N_INST 64
#define HW 64000   // 200*320
#define MASK_ELEMS (N_INST * HW)

#define TILE_P 256          // pixels per CTA tile
#define NTILES 250          // 64000 / 256
#define KC 16               // k-chunk (j rows) per stage

// Scratch (no cudaMalloc):
__device__ unsigned long long g_Odup[N_INST * N_INST];  // (O,O) pairs, [j][i]
__device__ float g_a[N_INST * 256];   // a_i[c] = relu(U[c,ki]) * P[c]
__device__ float g_b[N_INST * 256];   // b_i[c] = relu(V[c,ki])

__device__ __forceinline__ float sigmoidf_(float x) {
    return __fdividef(1.0f, 1.0f + __expf(-x));
}

__device__ __forceinline__ unsigned long long pack2_(float lo, float hi) {
    unsigned long long d;
    asm("mov.b64 %0, {%1, %2};" : "=l"(d) : "f"(lo), "f"(hi));
    return d;
}

__device__ __forceinline__ void unpack2_(unsigned long long v, float& lo, float& hi) {
    asm("mov.b64 {%0, %1}, %2;" : "=f"(lo), "=f"(hi) : "l"(v));
}

__device__ __forceinline__ unsigned long long fma2_(unsigned long long a,
                                                    unsigned long long b,
                                                    unsigned long long c) {
    unsigned long long d;
    asm("fma.rn.f32x2 %0, %1, %2, %3;" : "=l"(d) : "l"(a), "l"(b), "l"(c));
    return d;
}

// ---------------------------------------------------------------------------
// Kernel 0: gather. One warp per instance does the STRIDED class-column
// reads once, writing coalesced per-instance vectors a_i, b_i.
// ---------------------------------------------------------------------------
__global__ void gather_kernel(const int*   __restrict__ cls_idx,
                              const float* __restrict__ U_w,   // (256,80)
                              const float* __restrict__ V_w,   // (256,80)
                              const float* __restrict__ P_w)   // (384,)
{
    int w    = (blockIdx.x * blockDim.x + threadIdx.x) >> 5;
    int lane = threadIdx.x & 31;
    if (w >= N_INST) return;
    int k = cls_idx[w] - 1;

    #pragma unroll
    for (int c = lane; c < 256; c += 32) {
        float u = fmaxf(U_w[c * 80 + k], 0.f) * P_w[c];
        float v = fmaxf(V_w[c * 80 + k], 0.f);
        g_a[w * 256 + c] = u;
        g_b[w * 256 + c] = v;
    }
}

// ---------------------------------------------------------------------------
// Kernel 1: pairs. One warp per unordered pair (i<j); cls term is now a
// COALESCED dot over the gathered vectors. Both orientations at once.
// ---------------------------------------------------------------------------
__global__ void relation_O_kernel(const float* __restrict__ bbox,
                                  const float* __restrict__ Wc_w,  // (128,4)
                                  const float* __restrict__ P_w,   // (384,)
                                  float* __restrict__ out_O)
{
    int warp = (blockIdx.x * blockDim.x + threadIdx.x) >> 5;
    int lane = threadIdx.x & 31;
    const int NPAIR = (N_INST * (N_INST - 1)) / 2;   // 2016
    if (warp >= NPAIR + N_INST) return;

    if (warp >= NPAIR) {                              // diagonal zeros
        if (lane == 0) {
            int i = warp - NPAIR;
            out_O[i * 64 + i]  = 0.f;
            g_Odup[i * 64 + i] = 0ull;
        }
        return;
    }

    // decode i < j from triangular index: warp = j*(j-1)/2 + i
    int j = (int)((1.0f + sqrtf(8.0f * (float)warp + 1.0f)) * 0.5f);
    while (j * (j - 1) / 2 > warp) j--;
    while ((j + 1) * j / 2 <= warp) j++;
    int i = warp - j * (j - 1) / 2;

    float s_ij = 0.f, s_ji = 0.f;

    #pragma unroll
    for (int c = lane; c < 256; c += 32) {
        float ai = g_a[i * 256 + c];
        float aj = g_a[j * 256 + c];
        float bi = g_b[i * 256 + c];
        float bj = g_b[j * 256 + c];
        s_ij += ai * bj;      // relu(U·ki)·P · relu(V·kj)
        s_ji += aj * bi;
    }

    float x0i = bbox[i * 5 + 1], y0i = bbox[i * 5 + 2];
    float x1i = bbox[i * 5 + 3], y1i = bbox[i * 5 + 4];
    float x0j = bbox[j * 5 + 1], y0j = bbox[j * 5 + 2];
    float x1j = bbox[j * 5 + 3], y1j = bbox[j * 5 + 4];
    float wi = x1i - x0i + 1.f, hi = y1i - y0i + 1.f;
    float wj = x1j - x0j + 1.f, hj = y1j - y0j + 1.f;
    float xci = x0i + 0.5f * wi, yci = y0i + 0.5f * hi;
    float xcj = x0j + 0.5f * wj, ycj = y0j + 0.5f * hj;

    float dx_ij = -(xci - xcj) / wi, dy_ij = -(yci - ycj) / hi;
    float dw_ij = __logf(wj / wi),   dh_ij = __logf(hj / hi);
    float dx_ji = -(xcj - xci) / wj, dy_ji = -(ycj - yci) / hj;
    float dw_ji = __logf(wi / wj),   dh_ji = __logf(hi / hj);

    #pragma unroll
    for (int o = lane; o < 128; o += 32) {
        float4 w4 = *reinterpret_cast<const float4*>(&Wc_w[o * 4]);
        float p = P_w[256 + o];
        float a = dx_ij * w4.x + dy_ij * w4.y + dw_ij * w4.z + dh_ij * w4.w;
        float b = dx_ji * w4.x + dy_ji * w4.y + dw_ji * w4.z + dh_ji * w4.w;
        s_ij += fmaxf(a, 0.f) * p;
        s_ji += fmaxf(b, 0.f) * p;
    }

    #pragma unroll
    for (int off = 16; off; off >>= 1) {
        s_ij += __shfl_xor_sync(0xffffffffu, s_ij, off);
        s_ji += __shfl_xor_sync(0xffffffffu, s_ji, off);
    }

    if (lane == 0) {
        float r_ij = sigmoidf_(s_ij);
        float r_ji = sigmoidf_(s_ji);
        float o_ij = fmaxf(r_ij - r_ji, 0.f);
        float o_ji = fmaxf(r_ji - r_ij, 0.f);
        out_O[i * 64 + j]  = o_ij;
        out_O[j * 64 + i]  = o_ji;
        g_Odup[j * 64 + i] = pack2_(o_ij, o_ij);
        g_Odup[i * 64 + j] = pack2_(o_ji, o_ji);
    }
}

// ---------------------------------------------------------------------------
// Kernel 2: tiled GEMM (exact R9 winner).  w[i,p] = sum_j O[i,j]*t[j,p].
// CTA: all 64 i x 256 px; O dup'd table resident in smem; t staged in
// KC=16 chunks with sigma computed during staging; thread tile 8i x 8p.
// ---------------------------------------------------------------------------
__global__ void __launch_bounds__(256, 2)
mask_gemm_kernel(const float* __restrict__ mask, float* __restrict__ out)
{
    __shared__ __align__(16) unsigned long long Od[64 * 64];  // 32KB
    __shared__ __align__(16) float tS[KC * TILE_P];           // 16KB

    int tid  = threadIdx.x;
    int w    = tid >> 5;        // warp 0..7 -> i rows [w*8, w*8+8)
    int lane = tid & 31;        // pixel quads lane, lane+32
    int pbase = blockIdx.x * TILE_P;

    #pragma unroll
    for (int k = tid; k < 4096; k += 256) Od[k] = g_Odup[k];

    unsigned long long acc[32];
    #pragma unroll
    for (int k = 0; k < 32; k++) acc[k] = 0ull;

    #pragma unroll 1
    for (int kc = 0; kc < 4; kc++) {
        __syncthreads();   // smem free (covers Od copy on kc==0)
        #pragma unroll
        for (int s = tid; s < (KC * TILE_P) / 4; s += 256) {   // 1024 float4
            int row = s >> 6;
            int q   = s & 63;
            float4 m = *reinterpret_cast<const float4*>(
                mask + (size_t)(kc * KC + row) * HW + pbase + q * 4);
            float4 t;
            t.x = sigmoidf_(m.x);
            t.y = sigmoidf_(m.y);
            t.z = sigmoidf_(m.z);
            t.w = sigmoidf_(m.w);
            *reinterpret_cast<float4*>(&tS[row * TILE_P + q * 4]) = t;
        }
        __syncthreads();

        #pragma unroll
        for (int k = 0; k < KC; k++) {
            const ulonglong2* trow =
                reinterpret_cast<const ulonglong2*>(&tS[k * TILE_P]);
            ulonglong2 tA = trow[lane];
            ulonglong2 tB = trow[32 + lane];
            const ulonglong2* orow = reinterpret_cast<const ulonglong2*>(
                &Od[(kc * KC + k) * 64 + w * 8]);
            ulonglong2 o01 = orow[0];
            ulonglong2 o23 = orow[1];
            ulonglong2 o45 = orow[2];
            ulonglong2 o67 = orow[3];

            acc[ 0] = fma2_(o01.x, tA.x, acc[ 0]);
            acc[ 1] = fma2_(o01.x, tA.y, acc[ 1]);
            acc[ 2] = fma2_(o01.x, tB.x, acc[ 2]);
            acc[ 3] = fma2_(o01.x, tB.y, acc[ 3]);
            acc[ 4] = fma2_(o01.y, tA.x, acc[ 4]);
            acc[ 5] = fma2_(o01.y, tA.y, acc[ 5]);
            acc[ 6] = fma2_(o01.y, tB.x, acc[ 6]);
            acc[ 7] = fma2_(o01.y, tB.y, acc[ 7]);
            acc[ 8] = fma2_(o23.x, tA.x, acc[ 8]);
            acc[ 9] = fma2_(o23.x, tA.y, acc[ 9]);
            acc[10] = fma2_(o23.x, tB.x, acc[10]);
            acc[11] = fma2_(o23.x, tB.y, acc[11]);
            acc[12] = fma2_(o23.y, tA.x, acc[12]);
            acc[13] = fma2_(o23.y, tA.y, acc[13]);
            acc[14] = fma2_(o23.y, tB.x, acc[14]);
            acc[15] = fma2_(o23.y, tB.y, acc[15]);
            acc[16] = fma2_(o45.x, tA.x, acc[16]);
            acc[17] = fma2_(o45.x, tA.y, acc[17]);
            acc[18] = fma2_(o45.x, tB.x, acc[18]);
            acc[19] = fma2_(o45.x, tB.y, acc[19]);
            acc[20] = fma2_(o45.y, tA.x, acc[20]);
            acc[21] = fma2_(o45.y, tA.y, acc[21]);
            acc[22] = fma2_(o45.y, tB.x, acc[22]);
            acc[23] = fma2_(o45.y, tB.y, acc[23]);
            acc[24] = fma2_(o67.x, tA.x, acc[24]);
            acc[25] = fma2_(o67.x, tA.y, acc[25]);
            acc[26] = fma2_(o67.x, tB.x, acc[26]);
            acc[27] = fma2_(o67.x, tB.y, acc[27]);
            acc[28] = fma2_(o67.y, tA.x, acc[28]);
            acc[29] = fma2_(o67.y, tA.y, acc[29]);
            acc[30] = fma2_(o67.y, tB.x, acc[30]);
            acc[31] = fma2_(o67.y, tB.y, acc[31]);
        }
    }

    // epilogue: new = m - m * sigma(m) * w  (sigma recomputed)
    #pragma unroll
    for (int r = 0; r < 8; r++) {
        int i = w * 8 + r;
        size_t base = (size_t)i * HW + pbase;

        float4 mA = *reinterpret_cast<const float4*>(mask + base + lane * 4);
        float4 mB = *reinterpret_cast<const float4*>(mask + base + (32 + lane) * 4);

        float a0, a1, a2, a3, b0, b1, b2, b3;
        unpack2_(acc[r * 4 + 0], a0, a1);
        unpack2_(acc[r * 4 + 1], a2, a3);
        unpack2_(acc[r * 4 + 2], b0, b1);
        unpack2_(acc[r * 4 + 3], b2, b3);

        float4 rA, rB;
        rA.x = mA.x - mA.x * sigmoidf_(mA.x) * a0;
        rA.y = mA.y - mA.y * sigmoidf_(mA.y) * a1;
        rA.z = mA.z - mA.z * sigmoidf_(mA.z) * a2;
        rA.w = mA.w - mA.w * sigmoidf_(mA.w) * a3;
        rB.x = mB.x - mB.x * sigmoidf_(mB.x) * b0;
        rB.y = mB.y - mB.y * sigmoidf_(mB.y) * b1;
        rB.z = mB.z - mB.z * sigmoidf_(mB.z) * b2;
        rB.w = mB.w - mB.w * sigmoidf_(mB.w) * b3;

        *reinterpret_cast<float4*>(out + base + lane * 4)        = rA;
        *reinterpret_cast<float4*>(out + base + (32 + lane) * 4) = rB;
    }
}

extern "C" void kernel_launch(void* const* d_in, const int* in_sizes, int n_in,
                              void* d_out, int out_size)
{
    const float* mask    = (const float*)d_in[0];
    const float* bbox    = (const float*)d_in[1];
    const int*   cls_idx = (const int*)  d_in[2];
    const float* U_w     = (const float*)d_in[3];
    const float* V_w     = (const float*)d_in[4];
    const float* Wc_w    = (const float*)d_in[5];
    const float* P_w     = (const float*)d_in[6];

    float* out_mask = (float*)d_out;                 // 4,096,000 elems
    float* out_O    = (float*)d_out + MASK_ELEMS;    // 4,096 elems

    gather_kernel<<<8, 256>>>(cls_idx, U_w, V_w, P_w);
    relation_O_kernel<<<260, 256>>>(bbox, Wc_w, P_w, out_O);
    mask_gemm_kernel<<<NTILES, 256>>>(mask, out_mask);
}

// round 15
// speedup vs baseline: 1.2361x; 1.0767x over previous
#include <cuda_runtime.h>
#include <cstdint>

#define N_INST 64
#define HW 64000   // 200*320
#define MASK_ELEMS (N_INST * HW)

#define TILE_P 256          // pixels per CTA tile
#define NTILES 250          // 64000 / 256
#define KC 16               // k-chunk (j rows) per stage

// Scratch (no cudaMalloc):
__device__ unsigned long long g_Odup[N_INST * N_INST];  // (O,O) pairs, [j][i]
__device__ float g_a[N_INST * 256];   // a_i[c] = relu(U[c,ki]) * P[c]
__device__ float g_b[N_INST * 256];   // b_i[c] = relu(V[c,ki])

__device__ __forceinline__ float sigmoidf_(float x) {
    return __fdividef(1.0f, 1.0f + __expf(-x));
}

__device__ __forceinline__ unsigned long long pack2_(float lo, float hi) {
    unsigned long long d;
    asm("mov.b64 %0, {%1, %2};" : "=l"(d) : "f"(lo), "f"(hi));
    return d;
}

__device__ __forceinline__ void unpack2_(unsigned long long v, float& lo, float& hi) {
    asm("mov.b64 {%0, %1}, %2;" : "=f"(lo), "=f"(hi) : "l"(v));
}

__device__ __forceinline__ unsigned long long fma2_(unsigned long long a,
                                                    unsigned long long b,
                                                    unsigned long long c) {
    unsigned long long d;
    asm("fma.rn.f32x2 %0, %1, %2, %3;" : "=l"(d) : "l"(a), "l"(b), "l"(c));
    return d;
}

// ---------------------------------------------------------------------------
// Kernel 0: gather, fully parallel. Block b = instance b, thread t = channel.
// One (U,V) load pair per thread -> 16K-way MLP across 64 SMs.
// ---------------------------------------------------------------------------
__global__ void gather_kernel(const int*   __restrict__ cls_idx,
                              const float* __restrict__ U_w,   // (256,80)
                              const float* __restrict__ V_w,   // (256,80)
                              const float* __restrict__ P_w)   // (384,)
{
    int i = blockIdx.x;          // instance 0..63
    int c = threadIdx.x;         // channel 0..255
    int k = cls_idx[i] - 1;

    float u = fmaxf(U_w[c * 80 + k], 0.f) * P_w[c];
    float v = fmaxf(V_w[c * 80 + k], 0.f);
    g_a[i * 256 + c] = u;
    g_b[i * 256 + c] = v;
}

// ---------------------------------------------------------------------------
// Kernel 1: pairs. One warp per unordered pair (i<j); cls term is a
// COALESCED dot over the gathered vectors. Both orientations at once.
// ---------------------------------------------------------------------------
__global__ void relation_O_kernel(const float* __restrict__ bbox,
                                  const float* __restrict__ Wc_w,  // (128,4)
                                  const float* __restrict__ P_w,   // (384,)
                                  float* __restrict__ out_O)
{
    int warp = (blockIdx.x * blockDim.x + threadIdx.x) >> 5;
    int lane = threadIdx.x & 31;
    const int NPAIR = (N_INST * (N_INST - 1)) / 2;   // 2016
    if (warp >= NPAIR + N_INST) return;

    if (warp >= NPAIR) {                              // diagonal zeros
        if (lane == 0) {
            int i = warp - NPAIR;
            out_O[i * 64 + i]  = 0.f;
            g_Odup[i * 64 + i] = 0ull;
        }
        return;
    }

    // decode i < j from triangular index: warp = j*(j-1)/2 + i
    int j = (int)((1.0f + sqrtf(8.0f * (float)warp + 1.0f)) * 0.5f);
    while (j * (j - 1) / 2 > warp) j--;
    while ((j + 1) * j / 2 <= warp) j++;
    int i = warp - j * (j - 1) / 2;

    float s_ij = 0.f, s_ji = 0.f;

    #pragma unroll
    for (int c = lane; c < 256; c += 32) {
        float ai = g_a[i * 256 + c];
        float aj = g_a[j * 256 + c];
        float bi = g_b[i * 256 + c];
        float bj = g_b[j * 256 + c];
        s_ij += ai * bj;      // relu(U·ki)·P · relu(V·kj)
        s_ji += aj * bi;
    }

    float x0i = bbox[i * 5 + 1], y0i = bbox[i * 5 + 2];
    float x1i = bbox[i * 5 + 3], y1i = bbox[i * 5 + 4];
    float x0j = bbox[j * 5 + 1], y0j = bbox[j * 5 + 2];
    float x1j = bbox[j * 5 + 3], y1j = bbox[j * 5 + 4];
    float wi = x1i - x0i + 1.f, hi = y1i - y0i + 1.f;
    float wj = x1j - x0j + 1.f, hj = y1j - y0j + 1.f;
    float xci = x0i + 0.5f * wi, yci = y0i + 0.5f * hi;
    float xcj = x0j + 0.5f * wj, ycj = y0j + 0.5f * hj;

    float dx_ij = -(xci - xcj) / wi, dy_ij = -(yci - ycj) / hi;
    float dw_ij = __logf(wj / wi),   dh_ij = __logf(hj / hi);
    float dx_ji = -(xcj - xci) / wj, dy_ji = -(ycj - yci) / hj;
    float dw_ji = __logf(wi / wj),   dh_ji = __logf(hi / hj);

    #pragma unroll
    for (int o = lane; o < 128; o += 32) {
        float4 w4 = *reinterpret_cast<const float4*>(&Wc_w[o * 4]);
        float p = P_w[256 + o];
        float a = dx_ij * w4.x + dy_ij * w4.y + dw_ij * w4.z + dh_ij * w4.w;
        float b = dx_ji * w4.x + dy_ji * w4.y + dw_ji * w4.z + dh_ji * w4.w;
        s_ij += fmaxf(a, 0.f) * p;
        s_ji += fmaxf(b, 0.f) * p;
    }

    #pragma unroll
    for (int off = 16; off; off >>= 1) {
        s_ij += __shfl_xor_sync(0xffffffffu, s_ij, off);
        s_ji += __shfl_xor_sync(0xffffffffu, s_ji, off);
    }

    if (lane == 0) {
        float r_ij = sigmoidf_(s_ij);
        float r_ji = sigmoidf_(s_ji);
        float o_ij = fmaxf(r_ij - r_ji, 0.f);
        float o_ji = fmaxf(r_ji - r_ij, 0.f);
        out_O[i * 64 + j]  = o_ij;
        out_O[j * 64 + i]  = o_ji;
        g_Odup[j * 64 + i] = pack2_(o_ij, o_ij);
        g_Odup[i * 64 + j] = pack2_(o_ji, o_ji);
    }
}

// ---------------------------------------------------------------------------
// Kernel 2: tiled GEMM (exact R9 winner).  w[i,p] = sum_j O[i,j]*t[j,p].
// CTA: all 64 i x 256 px; O dup'd table resident in smem; t staged in
// KC=16 chunks with sigma computed during staging; thread tile 8i x 8p.
// ---------------------------------------------------------------------------
__global__ void __launch_bounds__(256, 2)
mask_gemm_kernel(const float* __restrict__ mask, float* __restrict__ out)
{
    __shared__ __align__(16) unsigned long long Od[64 * 64];  // 32KB
    __shared__ __align__(16) float tS[KC * TILE_P];           // 16KB

    int tid  = threadIdx.x;
    int w    = tid >> 5;        // warp 0..7 -> i rows [w*8, w*8+8)
    int lane = tid & 31;        // pixel quads lane, lane+32
    int pbase = blockIdx.x * TILE_P;

    #pragma unroll
    for (int k = tid; k < 4096; k += 256) Od[k] = g_Odup[k];

    unsigned long long acc[32];
    #pragma unroll
    for (int k = 0; k < 32; k++) acc[k] = 0ull;

    #pragma unroll 1
    for (int kc = 0; kc < 4; kc++) {
        __syncthreads();   // smem free (covers Od copy on kc==0)
        #pragma unroll
        for (int s = tid; s < (KC * TILE_P) / 4; s += 256) {   // 1024 float4
            int row = s >> 6;
            int q   = s & 63;
            float4 m = *reinterpret_cast<const float4*>(
                mask + (size_t)(kc * KC + row) * HW + pbase + q * 4);
            float4 t;
            t.x = sigmoidf_(m.x);
            t.y = sigmoidf_(m.y);
            t.z = sigmoidf_(m.z);
            t.w = sigmoidf_(m.w);
            *reinterpret_cast<float4*>(&tS[row * TILE_P + q * 4]) = t;
        }
        __syncthreads();

        #pragma unroll
        for (int k = 0; k < KC; k++) {
            const ulonglong2* trow =
                reinterpret_cast<const ulonglong2*>(&tS[k * TILE_P]);
            ulonglong2 tA = trow[lane];
            ulonglong2 tB = trow[32 + lane];
            const ulonglong2* orow = reinterpret_cast<const ulonglong2*>(
                &Od[(kc * KC + k) * 64 + w * 8]);
            ulonglong2 o01 = orow[0];
            ulonglong2 o23 = orow[1];
            ulonglong2 o45 = orow[2];
            ulonglong2 o67 = orow[3];

            acc[ 0] = fma2_(o01.x, tA.x, acc[ 0]);
            acc[ 1] = fma2_(o01.x, tA.y, acc[ 1]);
            acc[ 2] = fma2_(o01.x, tB.x, acc[ 2]);
            acc[ 3] = fma2_(o01.x, tB.y, acc[ 3]);
            acc[ 4] = fma2_(o01.y, tA.x, acc[ 4]);
            acc[ 5] = fma2_(o01.y, tA.y, acc[ 5]);
            acc[ 6] = fma2_(o01.y, tB.x, acc[ 6]);
            acc[ 7] = fma2_(o01.y, tB.y, acc[ 7]);
            acc[ 8] = fma2_(o23.x, tA.x, acc[ 8]);
            acc[ 9] = fma2_(o23.x, tA.y, acc[ 9]);
            acc[10] = fma2_(o23.x, tB.x, acc[10]);
            acc[11] = fma2_(o23.x, tB.y, acc[11]);
            acc[12] = fma2_(o23.y, tA.x, acc[12]);
            acc[13] = fma2_(o23.y, tA.y, acc[13]);
            acc[14] = fma2_(o23.y, tB.x, acc[14]);
            acc[15] = fma2_(o23.y, tB.y, acc[15]);
            acc[16] = fma2_(o45.x, tA.x, acc[16]);
            acc[17] = fma2_(o45.x, tA.y, acc[17]);
            acc[18] = fma2_(o45.x, tB.x, acc[18]);
            acc[19] = fma2_(o45.x, tB.y, acc[19]);
            acc[20] = fma2_(o45.y, tA.x, acc[20]);
            acc[21] = fma2_(o45.y, tA.y, acc[21]);
            acc[22] = fma2_(o45.y, tB.x, acc[22]);
            acc[23] = fma2_(o45.y, tB.y, acc[23]);
            acc[24] = fma2_(o67.x, tA.x, acc[24]);
            acc[25] = fma2_(o67.x, tA.y, acc[25]);
            acc[26] = fma2_(o67.x, tB.x, acc[26]);
            acc[27] = fma2_(o67.x, tB.y, acc[27]);
            acc[28] = fma2_(o67.y, tA.x, acc[28]);
            acc[29] = fma2_(o67.y, tA.y, acc[29]);
            acc[30] = fma2_(o67.y, tB.x, acc[30]);
            acc[31] = fma2_(o67.y, tB.y, acc[31]);
        }
    }

    // epilogue: new = m - m * sigma(m) * w  (sigma recomputed)
    #pragma unroll
    for (int r = 0; r < 8; r++) {
        int i = w * 8 + r;
        size_t base = (size_t)i * HW + pbase;

        float4 mA = *reinterpret_cast<const float4*>(mask + base + lane * 4);
        float4 mB = *reinterpret_cast<const float4*>(mask + base + (32 + lane) * 4);

        float a0, a1, a2, a3, b0, b1, b2, b3;
        unpack2_(acc[r * 4 + 0], a0, a1);
        unpack2_(acc[r * 4 + 1], a2, a3);
        unpack2_(acc[r * 4 + 2], b0, b1);
        unpack2_(acc[r * 4 + 3], b2, b3);

        float4 rA, rB;
        rA.x = mA.x - mA.x * sigmoidf_(mA.x) * a0;
        rA.y = mA.y - mA.y * sigmoidf_(mA.y) * a1;
        rA.z = mA.z - mA.z * sigmoidf_(mA.z) * a2;
        rA.w = mA.w - mA.w * sigmoidf_(mA.w) * a3;
        rB.x = mB.x - mB.x * sigmoidf_(mB.x) * b0;
        rB.y = mB.y - mB.y * sigmoidf_(mB.y) * b1;
        rB.z = mB.z - mB.z * sigmoidf_(mB.z) * b2;
        rB.w = mB.w - mB.w * sigmoidf_(mB.w) * b3;

        *reinterpret_cast<float4*>(out + base + lane * 4)        = rA;
        *reinterpret_cast<float4*>(out + base + (32 + lane) * 4) = rB;
    }
}

extern "C" void kernel_launch(void* const* d_in, const int* in_sizes, int n_in,
                              void* d_out, int out_size)
{
    const float* mask    = (const float*)d_in[0];
    const float* bbox    = (const float*)d_in[1];
    const int*   cls_idx = (const int*)  d_in[2];
    const float* U_w     = (const float*)d_in[3];
    const float* V_w     = (const float*)d_in[4];
    const float* Wc_w    = (const float*)d_in[5];
    const float* P_w     = (const float*)d_in[6];

    float* out_mask = (float*)d_out;                 // 4,096,000 elems
    float* out_O    = (float*)d_out + MASK_ELEMS;    // 4,096 elems

    gather_kernel<<<64, 256>>>(cls_idx, U_w, V_w, P_w);
    relation_O_kernel<<<260, 256>>>(bbox, Wc_w, P_w, out_O);
    mask_gemm_kernel<<<NTILES, 256>>>(mask, out_mask);
}